// round 9
// baseline (speedup 1.0000x reference)
#include <cuda_runtime.h>

// VectorQuantizer: z [B,64] f32, codebook [1024,64] f32
// out = concat( z_q_st [B*64], vq_loss [1], indices-as-float [B] )

typedef unsigned long long u64;

#define K_CODES 1024
#define D 64
#define NDP 32                 // dim-pairs
#define THREADS 256
#define ROWS_CTA 128
#define CHUNK 256              // codes staged per pass
#define NCHUNK (K_CODES/CHUNK)
#define WCODES 32              // codes per warp per chunk
#define TC 8                   // codes per register tile
#define TR 4                   // rows per lane

__device__ double   g_loss;
__device__ unsigned g_done;
__device__ float    g_c2[K_CODES];

static __device__ __forceinline__ u64 pack2(float x, float y) {
    u64 r; asm("mov.b64 %0,{%1,%2};" : "=l"(r) : "f"(x), "f"(y)); return r;
}
static __device__ __forceinline__ void unpack2(u64 v, float& x, float& y) {
    asm("mov.b64 {%0,%1},%2;" : "=f"(x), "=f"(y) : "l"(v));
}
static __device__ __forceinline__ u64 ffma2(u64 a, u64 b, u64 c) {
    u64 d; asm("fma.rn.f32x2 %0,%1,%2,%3;" : "=l"(d) : "l"(a), "l"(b), "l"(c)); return d;
}

// Prep: c2 per code (pairwise tree, unchanged since R1), zero loss + done counter.
__global__ void vq_prep(const float* __restrict__ cb) {
    __shared__ float s[D];
    int k = blockIdx.x, d = threadIdx.x;
    float v = cb[k * D + d];
    s[d] = v * v;
    __syncthreads();
#pragma unroll
    for (int off = D / 2; off >= 1; off >>= 1) {
        if (d < off) s[d] = s[d] + s[d + off];
        __syncthreads();
    }
    if (d == 0) {
        g_c2[k] = s[0];
        if (k == 0) { g_loss = 0.0; g_done = 0u; }
    }
}

__global__ void __launch_bounds__(THREADS, 2)
vq_main(const float* __restrict__ z, const float* __restrict__ cb,
        float* __restrict__ out, int B, int out_size) {
    extern __shared__ char smraw[];
    u64*   s_z  = (u64*)smraw;                 // [NDP][128] z transposed (dim-pair major)
    u64*   s_c  = s_z + NDP * ROWS_CTA;        // [NDP][256] codebook chunk transposed
    float* s_c2 = (float*)(s_c + NDP * CHUNK); // [1024]
    float* s_z2 = s_c2 + K_CODES;              // [128]
    // overlays inside s_c after mainloop:
    float*  candv = (float*)s_c;                         // [8][128]
    int*    candi = (int*)(candv + 8 * ROWS_CTA);        // [8][128]
    double* sd    = (double*)(candi + 8 * ROWS_CTA);     // [256]

    const int t    = threadIdx.x;
    const int lane = t & 31;
    const int w    = t >> 5;
    const long base = (long)blockIdx.x * ROWS_CTA;

    // ---- stage z transposed + z2 (R1 tree, bitwise) ----
    if (t < ROWS_CTA) {
        const float4* a4 = (const float4*)(z + (base + t) * D);
        float s[32];
#pragma unroll
        for (int i4 = 0; i4 < D / 4; i4++) {
            float4 a = a4[i4];
            s_z[(2 * i4 + 0) * ROWS_CTA + t] = pack2(a.x, a.y);
            s_z[(2 * i4 + 1) * ROWS_CTA + t] = pack2(a.z, a.w);
            s[2 * i4 + 0] = a.x * a.x + a.y * a.y;
            s[2 * i4 + 1] = a.z * a.z + a.w * a.w;
        }
#pragma unroll
        for (int off = 16; off >= 1; off >>= 1)
#pragma unroll
            for (int i = 0; i < off; i++) s[i] = s[i] + s[i + off];
        s_z2[t] = s[0];
    }
#pragma unroll
    for (int i = t; i < K_CODES; i += THREADS) s_c2[i] = g_c2[i];
    __syncthreads();

    // this lane's 4 rows: local rows lane*4 .. +3
    float zz0 = s_z2[lane * 4 + 0], zz1 = s_z2[lane * 4 + 1];
    float zz2 = s_z2[lane * 4 + 2], zz3 = s_z2[lane * 4 + 3];

    float mv0 = 3.402823466e38f, mv1 = mv0, mv2 = mv0, mv3 = mv0;
    int   mi0 = 0, mi1 = 0, mi2 = 0, mi3 = 0;

    for (int ch = 0; ch < NCHUNK; ++ch) {
        __syncthreads();
        // stage codebook chunk transposed: s_c[dp][code]
        {
            const float4* src = (const float4*)(cb + (size_t)ch * CHUNK * D);
#pragma unroll
            for (int it = 0; it < CHUNK * (D / 4) / THREADS; it++) {
                int p = it * THREADS + t;      // p = code*16 + f4
                int code = p >> 4;
                int f4 = p & 15;
                float4 v = src[p];
                s_c[(2 * f4 + 0) * CHUNK + code] = pack2(v.x, v.y);
                s_c[(2 * f4 + 1) * CHUNK + code] = pack2(v.z, v.w);
            }
        }
        __syncthreads();

        const int kwarp = ch * CHUNK + w * WCODES;   // global code base for this warp
#pragma unroll
        for (int tile = 0; tile < WCODES / TC; tile++) {
            const int kb = w * WCODES + tile * TC;   // code offset within chunk
            u64 a0[TC], a1[TC], a2[TC], a3[TC];
#pragma unroll
            for (int j = 0; j < TC; j++) { a0[j] = 0ull; a1[j] = 0ull; a2[j] = 0ull; a3[j] = 0ull; }

#pragma unroll
            for (int dp = 0; dp < NDP; dp++) {
                const u64* zrow = s_z + (size_t)dp * ROWS_CTA + lane * 4;
                ulonglong2 zp0 = *(const ulonglong2*)zrow;        // rows 0,1
                ulonglong2 zp1 = *(const ulonglong2*)(zrow + 2);  // rows 2,3
                const u64* crow = s_c + (size_t)dp * CHUNK + kb;
                ulonglong2 c0 = *(const ulonglong2*)(crow + 0);
                ulonglong2 c1 = *(const ulonglong2*)(crow + 2);
                ulonglong2 c2q = *(const ulonglong2*)(crow + 4);
                ulonglong2 c3 = *(const ulonglong2*)(crow + 6);
                u64 cv[TC] = { c0.x, c0.y, c1.x, c1.y, c2q.x, c2q.y, c3.x, c3.y };
#pragma unroll
                for (int j = 0; j < TC; j++) {
                    a0[j] = ffma2(zp0.x, cv[j], a0[j]);
                    a1[j] = ffma2(zp0.y, cv[j], a1[j]);
                    a2[j] = ffma2(zp1.x, cv[j], a2[j]);
                    a3[j] = ffma2(zp1.y, cv[j], a3[j]);
                }
            }

#pragma unroll
            for (int j = 0; j < TC; j++) {
                const int k = kwarp + tile * TC + j;
                const float c2s = s_c2[k];
                float e, o;
                unpack2(a0[j], e, o);
                float d0 = fmaf(-2.0f, e + o, zz0) + c2s;   // 2*cross exact (power of 2)
                if (d0 < mv0) { mv0 = d0; mi0 = k; }        // strict < => first index
                unpack2(a1[j], e, o);
                float d1 = fmaf(-2.0f, e + o, zz1) + c2s;
                if (d1 < mv1) { mv1 = d1; mi1 = k; }
                unpack2(a2[j], e, o);
                float d2 = fmaf(-2.0f, e + o, zz2) + c2s;
                if (d2 < mv2) { mv2 = d2; mi2 = k; }
                unpack2(a3[j], e, o);
                float d3 = fmaf(-2.0f, e + o, zz3) + c2s;
                if (d3 < mv3) { mv3 = d3; mi3 = k; }
            }
        }
    }

    // ---- cross-warp argmin combine (8 warps per row), idx tie-break ----
    __syncthreads();   // all warps done reading s_c -> safe to overlay
    candv[w * ROWS_CTA + lane * 4 + 0] = mv0;  candi[w * ROWS_CTA + lane * 4 + 0] = mi0;
    candv[w * ROWS_CTA + lane * 4 + 1] = mv1;  candi[w * ROWS_CTA + lane * 4 + 1] = mi1;
    candv[w * ROWS_CTA + lane * 4 + 2] = mv2;  candi[w * ROWS_CTA + lane * 4 + 2] = mi2;
    candv[w * ROWS_CTA + lane * 4 + 3] = mv3;  candi[w * ROWS_CTA + lane * 4 + 3] = mi3;
    __syncthreads();

    double lacc = 0.0;
    if (t < ROWS_CTA) {
        float bv = candv[t];
        int   bi = candi[t];
#pragma unroll
        for (int ww = 1; ww < 8; ww++) {
            float v = candv[ww * ROWS_CTA + t];
            int   i = candi[ww * ROWS_CTA + t];
            if (v < bv || (v == bv && i < bi)) { bv = v; bi = i; }
        }
        const long row = base + t;
        const float4* q = (const float4*)(cb + (size_t)bi * D);
        float4* o = (float4*)(out + row * D);
#pragma unroll
        for (int i4 = 0; i4 < D / 4; i4++) {
            float4 a = q[i4];
            float x, y, u, v2, d;
            unpack2(s_z[(2 * i4 + 0) * ROWS_CTA + t], x, y);
            unpack2(s_z[(2 * i4 + 1) * ROWS_CTA + t], u, v2);
            d = a.x - x;  lacc += (double)(d * d);
            d = a.y - y;  lacc += (double)(d * d);
            d = a.z - u;  lacc += (double)(d * d);
            d = a.w - v2; lacc += (double)(d * d);
            o[i4] = a;
        }
        if ((long)out_size >= (long)B * D + 1 + B)
            out[(long)B * D + 1 + row] = (float)bi;
    }

    // ---- block-reduce loss, last CTA finalizes ----
    __syncthreads();
    sd[t] = lacc;
    __syncthreads();
#pragma unroll
    for (int off = THREADS / 2; off >= 1; off >>= 1) {
        if (t < off) sd[t] += sd[t + off];
        __syncthreads();
    }
    if (t == 0) {
        atomicAdd(&g_loss, sd[0]);
        __threadfence();
        unsigned v = atomicAdd(&g_done, 1u);
        if (v == gridDim.x - 1) {
            g_done = 0u;
            if ((long)out_size >= (long)B * D + 1) {
                float m = (float)(g_loss / (double)((long)B * D));
                out[(size_t)B * D] = m + 0.25f * m;
            }
        }
    }
}

extern "C" void kernel_launch(void* const* d_in, const int* in_sizes, int n_in,
                              void* d_out, int out_size) {
    const float* z  = (const float*)d_in[0];
    const float* cb = (const float*)d_in[1];
    float* out = (float*)d_out;
    const int B = in_sizes[0] / D;

    const size_t smem = (size_t)NDP * ROWS_CTA * 8 + (size_t)NDP * CHUNK * 8
                      + K_CODES * 4 + ROWS_CTA * 4;
    cudaFuncSetAttribute(vq_main, cudaFuncAttributeMaxDynamicSharedMemorySize, (int)smem);

    vq_prep<<<K_CODES, D>>>(cb);
    vq_main<<<B / ROWS_CTA, THREADS, smem>>>(z, cb, out, B, out_size);
}

// round 10
// speedup vs baseline: 2.4542x; 2.4542x over previous
#include <cuda_runtime.h>

// VectorQuantizer: z [B,64] f32, codebook [1024,64] f32
// out = concat( z_q_st [B*64], vq_loss [1], indices-as-float [B] )

typedef unsigned long long u64;

#define K_CODES 1024
#define D 64
#define THREADS 128
#define RPT 2                       // rows per thread
#define ROWS_CTA (THREADS*RPT)      // 256
#define CHUNK 256                   // codes staged in smem per pass
#define NCHUNK (K_CODES/CHUNK)
#define KB 4                        // codes per register tile

__device__ double   g_loss;
__device__ unsigned g_done;
__device__ float    g_c2[K_CODES];  // per-code squared norm (pairwise tree)

static __device__ __forceinline__ u64 pack2(float x, float y) {
    u64 r; asm("mov.b64 %0,{%1,%2};" : "=l"(r) : "f"(x), "f"(y)); return r;
}
static __device__ __forceinline__ void unpack2(u64 v, float& x, float& y) {
    asm("mov.b64 {%0,%1},%2;" : "=f"(x), "=f"(y) : "l"(v));
}
static __device__ __forceinline__ u64 ffma2(u64 a, u64 b, u64 c) {
    u64 d; asm("fma.rn.f32x2 %0,%1,%2,%3;" : "=l"(d) : "l"(a), "l"(b), "l"(c)); return d;
}

// Prep: c2 (pairwise tree, bitwise stable since R1), zero loss + done counter.
__global__ void vq_prep(const float* __restrict__ cb) {
    __shared__ float s[D];
    int k = blockIdx.x, d = threadIdx.x;
    float v = cb[k * D + d];
    s[d] = v * v;
    __syncthreads();
#pragma unroll
    for (int off = D / 2; off >= 1; off >>= 1) {
        if (d < off) s[d] = s[d] + s[d + off];
        __syncthreads();
    }
    if (d == 0) {
        g_c2[k] = s[0];
        if (k == 0) { g_loss = 0.0; g_done = 0u; }
    }
}

// z2 for one row held as packed pairs: reproduces the reference pairwise tree bitwise.
static __device__ __forceinline__ float z2_of(const u64* zp) {
    float s[32];
#pragma unroll
    for (int i = 0; i < 16; i++) {
        float a, b, c, d;
        unpack2(zp[2 * i],     a, b);
        unpack2(zp[2 * i + 1], c, d);
        s[2 * i]     = a * a + b * b;
        s[2 * i + 1] = c * c + d * d;
    }
#pragma unroll
    for (int off = 16; off >= 1; off >>= 1)
#pragma unroll
        for (int i = 0; i < off; i++) s[i] = s[i] + s[i + off];
    return s[0];
}

__global__ void __launch_bounds__(THREADS, 3)
vq_main(const float* __restrict__ z, const float* __restrict__ cb,
        float* __restrict__ out, int B, int out_size) {
    extern __shared__ float sm[];
    float* s_c  = sm;               // [CHUNK][D] row-major codebook chunk
    float* s_c2 = sm + CHUNK * D;   // [1024] all c2 (staged once)

    const int t = threadIdx.x;
    const long base = (long)blockIdx.x * ROWS_CTA;
    const long rowA = base + t;
    const long rowB = base + THREADS + t;

    // Load both z rows packed as {z_2i, z_2i+1} pairs (one-time packing)
    u64 zpA[D / 2], zpB[D / 2];
    {
        const float4* a4 = (const float4*)(z + rowA * D);
        const float4* b4 = (const float4*)(z + rowB * D);
#pragma unroll
        for (int i = 0; i < D / 4; i++) {
            float4 a = a4[i];
            zpA[2 * i + 0] = pack2(a.x, a.y);
            zpA[2 * i + 1] = pack2(a.z, a.w);
            float4 b = b4[i];
            zpB[2 * i + 0] = pack2(b.x, b.y);
            zpB[2 * i + 1] = pack2(b.z, b.w);
        }
    }
    const float z2A = z2_of(zpA);
    const float z2B = z2_of(zpB);

    // stage all c2 once
#pragma unroll
    for (int i = t; i < K_CODES; i += THREADS) s_c2[i] = g_c2[i];

    float mvA = 3.402823466e38f, mvB = 3.402823466e38f;
    int   miA = 0, miB = 0;

    for (int ch = 0; ch < NCHUNK; ++ch) {
        __syncthreads();
        // Stage codebook chunk row-major straight from global (coalesced float4)
        {
            const float4* src = (const float4*)(cb + (size_t)ch * CHUNK * D);
            float4* dst = (float4*)s_c;
#pragma unroll 8
            for (int i = t; i < CHUNK * D / 4; i += THREADS) dst[i] = src[i];
        }
        __syncthreads();

        const int kbase = ch * CHUNK;
        for (int kb = 0; kb < CHUNK; kb += KB) {
            u64 accA[KB], accB[KB];
#pragma unroll
            for (int j = 0; j < KB; j++) { accA[j] = 0ull; accB[j] = 0ull; }

            // lane0 accumulates even dims, lane1 odd dims (bitwise same as R4)
#pragma unroll
            for (int i = 0; i < D / 4; i++) {
#pragma unroll
                for (int j = 0; j < KB; j++) {
                    ulonglong2 c = *(const ulonglong2*)(s_c + (size_t)(kb + j) * D + 4 * i);
                    accA[j] = ffma2(zpA[2 * i],     c.x, accA[j]);
                    accA[j] = ffma2(zpA[2 * i + 1], c.y, accA[j]);
                    accB[j] = ffma2(zpB[2 * i],     c.x, accB[j]);
                    accB[j] = ffma2(zpB[2 * i + 1], c.y, accB[j]);
                }
            }
#pragma unroll
            for (int j = 0; j < KB; j++) {
                int k = kbase + kb + j;
                float c2v = s_c2[k];
                float e, o;
                unpack2(accA[j], e, o);
                float dA = fmaf(-2.0f, e + o, z2A) + c2v;   // 2*cross exact (power of 2)
                if (dA < mvA) { mvA = dA; miA = k; }        // strict < => first index wins
                unpack2(accB[j], e, o);
                float dB = fmaf(-2.0f, e + o, z2B) + c2v;
                if (dB < mvB) { mvB = dB; miB = k; }
            }
        }
    }

    // Epilogue: gather z_q, write out, loss partials in double
    double lacc = 0.0;
    {
        const float4* qA = (const float4*)(cb + (size_t)miA * D);
        const float4* qB = (const float4*)(cb + (size_t)miB * D);
        float4* oA = (float4*)(out + rowA * D);
        float4* oB = (float4*)(out + rowB * D);
#pragma unroll
        for (int i = 0; i < D / 4; i++) {
            float4 a = qA[i];
            float x, y, u, w, d;
            unpack2(zpA[2 * i],     x, y);
            unpack2(zpA[2 * i + 1], u, w);
            d = a.x - x; lacc += (double)(d * d);
            d = a.y - y; lacc += (double)(d * d);
            d = a.z - u; lacc += (double)(d * d);
            d = a.w - w; lacc += (double)(d * d);
            oA[i] = a;
            float4 b = qB[i];
            unpack2(zpB[2 * i],     x, y);
            unpack2(zpB[2 * i + 1], u, w);
            d = b.x - x; lacc += (double)(d * d);
            d = b.y - y; lacc += (double)(d * d);
            d = b.z - u; lacc += (double)(d * d);
            d = b.w - w; lacc += (double)(d * d);
            oB[i] = b;
        }
    }

    if ((long)out_size >= (long)B * D + 1 + B) {
        const long iofs = (long)B * D + 1;
        out[iofs + rowA] = (float)miA;
        out[iofs + rowB] = (float)miB;
    }

    // block-reduce loss partials (reuse smem), one atomic per CTA
    __syncthreads();
    double* sd = (double*)sm;
    sd[t] = lacc;
    __syncthreads();
#pragma unroll
    for (int off = THREADS / 2; off >= 1; off >>= 1) {
        if (t < off) sd[t] += sd[t + off];
        __syncthreads();
    }
    if (t == 0) {
        atomicAdd(&g_loss, sd[0]);
        __threadfence();
        unsigned v = atomicAdd(&g_done, 1u);
        if (v == gridDim.x - 1) {       // last CTA finalizes loss
            g_done = 0u;
            if ((long)out_size >= (long)B * D + 1) {
                float m = (float)(g_loss / (double)((long)B * D));
                out[(size_t)B * D] = m + 0.25f * m;
            }
        }
    }
}

extern "C" void kernel_launch(void* const* d_in, const int* in_sizes, int n_in,
                              void* d_out, int out_size) {
    const float* z  = (const float*)d_in[0];
    const float* cb = (const float*)d_in[1];
    float* out = (float*)d_out;
    const int B = in_sizes[0] / D;

    const size_t smem = (size_t)CHUNK * D * sizeof(float) + K_CODES * sizeof(float);
    cudaFuncSetAttribute(vq_main, cudaFuncAttributeMaxDynamicSharedMemorySize, (int)smem);

    vq_prep<<<K_CODES, D>>>(cb);
    vq_main<<<B / ROWS_CTA, THREADS, smem>>>(z, cb, out, B, out_size);
}

// round 11
// speedup vs baseline: 3.0606x; 1.2471x over previous
#include <cuda_runtime.h>

// VectorQuantizer: z [B,64] f32, codebook [1024,64] f32
// out = concat( z_q_st [B*64], vq_loss [1], indices-as-float [B] )

typedef unsigned long long u64;

#define K_CODES 1024
#define D 64
#define THREADS 128
#define RPT 2                       // rows per thread
#define ROWS_CTA (THREADS*RPT)      // 256
#define CHUNK 256                   // codes staged in smem per pass
#define NCHUNK (K_CODES/CHUNK)
#define KB 8                        // codes per register tile (16 indep FFMA2 chains)

__device__ double   g_loss;
__device__ unsigned g_done;
__device__ float    g_c2[K_CODES];  // per-code squared norm (pairwise tree)

static __device__ __forceinline__ u64 pack2(float x, float y) {
    u64 r; asm("mov.b64 %0,{%1,%2};" : "=l"(r) : "f"(x), "f"(y)); return r;
}
static __device__ __forceinline__ void unpack2(u64 v, float& x, float& y) {
    asm("mov.b64 {%0,%1},%2;" : "=f"(x), "=f"(y) : "l"(v));
}
static __device__ __forceinline__ u64 ffma2(u64 a, u64 b, u64 c) {
    u64 d; asm("fma.rn.f32x2 %0,%1,%2,%3;" : "=l"(d) : "l"(a), "l"(b), "l"(c)); return d;
}

// Prep: c2 (pairwise tree, bitwise stable since R1), zero loss + done counter.
__global__ void vq_prep(const float* __restrict__ cb) {
    __shared__ float s[D];
    int k = blockIdx.x, d = threadIdx.x;
    float v = cb[k * D + d];
    s[d] = v * v;
    __syncthreads();
#pragma unroll
    for (int off = D / 2; off >= 1; off >>= 1) {
        if (d < off) s[d] = s[d] + s[d + off];
        __syncthreads();
    }
    if (d == 0) {
        g_c2[k] = s[0];
        if (k == 0) { g_loss = 0.0; g_done = 0u; }
    }
}

// z2 for one row held as packed pairs: reproduces the reference pairwise tree bitwise.
static __device__ __forceinline__ float z2_of(const u64* zp) {
    float s[32];
#pragma unroll
    for (int i = 0; i < 16; i++) {
        float a, b, c, d;
        unpack2(zp[2 * i],     a, b);
        unpack2(zp[2 * i + 1], c, d);
        s[2 * i]     = a * a + b * b;
        s[2 * i + 1] = c * c + d * d;
    }
#pragma unroll
    for (int off = 16; off >= 1; off >>= 1)
#pragma unroll
        for (int i = 0; i < off; i++) s[i] = s[i] + s[i + off];
    return s[0];
}

__global__ void __launch_bounds__(THREADS, 2)
vq_main(const float* __restrict__ z, const float* __restrict__ cb,
        float* __restrict__ out, int B, int out_size) {
    extern __shared__ float sm[];
    float* s_c  = sm;               // [CHUNK][D] row-major codebook chunk
    float* s_c2 = sm + CHUNK * D;   // [1024] all c2 (staged once)

    const int t = threadIdx.x;
    const long base = (long)blockIdx.x * ROWS_CTA;
    const long rowA = base + t;
    const long rowB = base + THREADS + t;

    // Load both z rows packed as {z_2i, z_2i+1} pairs (one-time packing)
    u64 zpA[D / 2], zpB[D / 2];
    {
        const float4* a4 = (const float4*)(z + rowA * D);
        const float4* b4 = (const float4*)(z + rowB * D);
#pragma unroll
        for (int i = 0; i < D / 4; i++) {
            float4 a = a4[i];
            zpA[2 * i + 0] = pack2(a.x, a.y);
            zpA[2 * i + 1] = pack2(a.z, a.w);
            float4 b = b4[i];
            zpB[2 * i + 0] = pack2(b.x, b.y);
            zpB[2 * i + 1] = pack2(b.z, b.w);
        }
    }
    const float z2A = z2_of(zpA);
    const float z2B = z2_of(zpB);

    // stage all c2 once
#pragma unroll
    for (int i = t; i < K_CODES; i += THREADS) s_c2[i] = g_c2[i];

    float mvA = 3.402823466e38f, mvB = 3.402823466e38f;
    int   miA = 0, miB = 0;

    for (int ch = 0; ch < NCHUNK; ++ch) {
        __syncthreads();
        // Stage codebook chunk row-major straight from global (coalesced float4)
        {
            const float4* src = (const float4*)(cb + (size_t)ch * CHUNK * D);
            float4* dst = (float4*)s_c;
#pragma unroll 8
            for (int i = t; i < CHUNK * D / 4; i += THREADS) dst[i] = src[i];
        }
        __syncthreads();

        const int kbase = ch * CHUNK;
        for (int kb = 0; kb < CHUNK; kb += KB) {
            u64 accA[KB], accB[KB];
#pragma unroll
            for (int j = 0; j < KB; j++) { accA[j] = 0ull; accB[j] = 0ull; }

            // lane0 accumulates even dims, lane1 odd dims (bitwise same as R4)
#pragma unroll
            for (int i = 0; i < D / 4; i++) {
                u64 zA0 = zpA[2 * i], zA1 = zpA[2 * i + 1];
                u64 zB0 = zpB[2 * i], zB1 = zpB[2 * i + 1];
#pragma unroll
                for (int j = 0; j < KB; j++) {
                    ulonglong2 c = *(const ulonglong2*)(s_c + (size_t)(kb + j) * D + 4 * i);
                    accA[j] = ffma2(zA0, c.x, accA[j]);
                    accA[j] = ffma2(zA1, c.y, accA[j]);
                    accB[j] = ffma2(zB0, c.x, accB[j]);
                    accB[j] = ffma2(zB1, c.y, accB[j]);
                }
            }
#pragma unroll
            for (int j = 0; j < KB; j++) {
                int k = kbase + kb + j;
                float c2v = s_c2[k];
                float e, o;
                unpack2(accA[j], e, o);
                float dA = fmaf(-2.0f, e + o, z2A) + c2v;   // 2*cross exact (power of 2)
                if (dA < mvA) { mvA = dA; miA = k; }        // strict < => first index wins
                unpack2(accB[j], e, o);
                float dB = fmaf(-2.0f, e + o, z2B) + c2v;
                if (dB < mvB) { mvB = dB; miB = k; }
            }
        }
    }

    // Epilogue: gather z_q, write out, loss partials in double
    double lacc = 0.0;
    {
        const float4* qA = (const float4*)(cb + (size_t)miA * D);
        const float4* qB = (const float4*)(cb + (size_t)miB * D);
        float4* oA = (float4*)(out + rowA * D);
        float4* oB = (float4*)(out + rowB * D);
#pragma unroll
        for (int i = 0; i < D / 4; i++) {
            float4 a = qA[i];
            float x, y, u, w, d;
            unpack2(zpA[2 * i],     x, y);
            unpack2(zpA[2 * i + 1], u, w);
            d = a.x - x; lacc += (double)(d * d);
            d = a.y - y; lacc += (double)(d * d);
            d = a.z - u; lacc += (double)(d * d);
            d = a.w - w; lacc += (double)(d * d);
            oA[i] = a;
            float4 b = qB[i];
            unpack2(zpB[2 * i],     x, y);
            unpack2(zpB[2 * i + 1], u, w);
            d = b.x - x; lacc += (double)(d * d);
            d = b.y - y; lacc += (double)(d * d);
            d = b.z - u; lacc += (double)(d * d);
            d = b.w - w; lacc += (double)(d * d);
            oB[i] = b;
        }
    }

    if ((long)out_size >= (long)B * D + 1 + B) {
        const long iofs = (long)B * D + 1;
        out[iofs + rowA] = (float)miA;
        out[iofs + rowB] = (float)miB;
    }

    // block-reduce loss partials (reuse smem), one atomic per CTA
    __syncthreads();
    double* sd = (double*)sm;
    sd[t] = lacc;
    __syncthreads();
#pragma unroll
    for (int off = THREADS / 2; off >= 1; off >>= 1) {
        if (t < off) sd[t] += sd[t + off];
        __syncthreads();
    }
    if (t == 0) {
        atomicAdd(&g_loss, sd[0]);
        __threadfence();
        unsigned v = atomicAdd(&g_done, 1u);
        if (v == gridDim.x - 1) {       // last CTA finalizes loss
            g_done = 0u;
            if ((long)out_size >= (long)B * D + 1) {
                float m = (float)(g_loss / (double)((long)B * D));
                out[(size_t)B * D] = m + 0.25f * m;
            }
        }
    }
}

extern "C" void kernel_launch(void* const* d_in, const int* in_sizes, int n_in,
                              void* d_out, int out_size) {
    const float* z  = (const float*)d_in[0];
    const float* cb = (const float*)d_in[1];
    float* out = (float*)d_out;
    const int B = in_sizes[0] / D;

    const size_t smem = (size_t)CHUNK * D * sizeof(float) + K_CODES * sizeof(float);
    cudaFuncSetAttribute(vq_main, cudaFuncAttributeMaxDynamicSharedMemorySize, (int)smem);

    vq_prep<<<K_CODES, D>>>(cb);
    vq_main<<<B / ROWS_CTA, THREADS, smem>>>(z, cb, out, B, out_size);
}

// round 12
// speedup vs baseline: 3.0617x; 1.0004x over previous
#include <cuda_runtime.h>

// VectorQuantizer: z [B,64] f32, codebook [1024,64] f32
// out = concat( z_q_st [B*64], vq_loss [1], indices-as-float [B] )

typedef unsigned long long u64;

#define K_CODES 1024
#define D 64
#define THREADS 128
#define RPT 2                       // rows per thread
#define ROWS_CTA (THREADS*RPT)      // 256
#define CHUNK 256                   // codes staged in smem per pass
#define NCHUNK (K_CODES/CHUNK)
#define KB 8                        // codes per register tile (16 indep FFMA2 chains)

__device__ double   g_loss;
__device__ unsigned g_done;
__device__ float    g_c2[K_CODES];  // per-code squared norm (pairwise tree)

static __device__ __forceinline__ u64 pack2(float x, float y) {
    u64 r; asm("mov.b64 %0,{%1,%2};" : "=l"(r) : "f"(x), "f"(y)); return r;
}
static __device__ __forceinline__ void unpack2(u64 v, float& x, float& y) {
    asm("mov.b64 {%0,%1},%2;" : "=f"(x), "=f"(y) : "l"(v));
}
static __device__ __forceinline__ u64 ffma2(u64 a, u64 b, u64 c) {
    u64 d; asm("fma.rn.f32x2 %0,%1,%2,%3;" : "=l"(d) : "l"(a), "l"(b), "l"(c)); return d;
}

// Prep: c2 (pairwise tree, bitwise stable since R1), zero loss + done counter.
__global__ void vq_prep(const float* __restrict__ cb) {
    __shared__ float s[D];
    int k = blockIdx.x, d = threadIdx.x;
    float v = cb[k * D + d];
    s[d] = v * v;
    __syncthreads();
#pragma unroll
    for (int off = D / 2; off >= 1; off >>= 1) {
        if (d < off) s[d] = s[d] + s[d + off];
        __syncthreads();
    }
    if (d == 0) {
        g_c2[k] = s[0];
        if (k == 0) { g_loss = 0.0; g_done = 0u; }
    }
}

// z2 for one row held as packed pairs: reproduces the reference pairwise tree bitwise.
static __device__ __forceinline__ float z2_of(const u64* zp) {
    float s[32];
#pragma unroll
    for (int i = 0; i < 16; i++) {
        float a, b, c, d;
        unpack2(zp[2 * i],     a, b);
        unpack2(zp[2 * i + 1], c, d);
        s[2 * i]     = a * a + b * b;
        s[2 * i + 1] = c * c + d * d;
    }
#pragma unroll
    for (int off = 16; off >= 1; off >>= 1)
#pragma unroll
        for (int i = 0; i < off; i++) s[i] = s[i] + s[i + off];
    return s[0];
}

__global__ void __launch_bounds__(THREADS, 2)
vq_main(const float* __restrict__ z, const float* __restrict__ cb,
        float* __restrict__ out, int B, int out_size) {
    extern __shared__ float sm[];
    float* s_c  = sm;               // [CHUNK][D] row-major codebook chunk
    float* s_c2 = sm + CHUNK * D;   // [1024] all c2 (staged once)

    const int t = threadIdx.x;
    const long base = (long)blockIdx.x * ROWS_CTA;
    const long rowA = base + t;
    const long rowB = base + THREADS + t;

    // Load both z rows packed as {z_2i, z_2i+1} pairs (one-time packing)
    u64 zpA[D / 2], zpB[D / 2];
    {
        const float4* a4 = (const float4*)(z + rowA * D);
        const float4* b4 = (const float4*)(z + rowB * D);
#pragma unroll
        for (int i = 0; i < D / 4; i++) {
            float4 a = a4[i];
            zpA[2 * i + 0] = pack2(a.x, a.y);
            zpA[2 * i + 1] = pack2(a.z, a.w);
            float4 b = b4[i];
            zpB[2 * i + 0] = pack2(b.x, b.y);
            zpB[2 * i + 1] = pack2(b.z, b.w);
        }
    }
    const float z2A = z2_of(zpA);
    const float z2B = z2_of(zpB);

    // stage all c2 once
#pragma unroll
    for (int i = t; i < K_CODES; i += THREADS) s_c2[i] = g_c2[i];

    float mvA = 3.402823466e38f, mvB = 3.402823466e38f;
    int   miA = 0, miB = 0;

    for (int ch = 0; ch < NCHUNK; ++ch) {
        __syncthreads();
        // Stage codebook chunk row-major straight from global (coalesced float4)
        {
            const float4* src = (const float4*)(cb + (size_t)ch * CHUNK * D);
            float4* dst = (float4*)s_c;
#pragma unroll 8
            for (int i = t; i < CHUNK * D / 4; i += THREADS) dst[i] = src[i];
        }
        __syncthreads();

        const int kbase = ch * CHUNK;
        for (int kb = 0; kb < CHUNK; kb += KB) {
            u64 accA[KB], accB[KB];
#pragma unroll
            for (int j = 0; j < KB; j++) { accA[j] = 0ull; accB[j] = 0ull; }

            // lane0 accumulates even dims, lane1 odd dims (bitwise same as R4)
#pragma unroll
            for (int i = 0; i < D / 4; i++) {
                u64 zA0 = zpA[2 * i], zA1 = zpA[2 * i + 1];
                u64 zB0 = zpB[2 * i], zB1 = zpB[2 * i + 1];
#pragma unroll
                for (int j = 0; j < KB; j++) {
                    ulonglong2 c = *(const ulonglong2*)(s_c + (size_t)(kb + j) * D + 4 * i);
                    accA[j] = ffma2(zA0, c.x, accA[j]);
                    accA[j] = ffma2(zA1, c.y, accA[j]);
                    accB[j] = ffma2(zB0, c.x, accB[j]);
                    accB[j] = ffma2(zB1, c.y, accB[j]);
                }
            }
#pragma unroll
            for (int j = 0; j < KB; j++) {
                int k = kbase + kb + j;
                float c2v = s_c2[k];
                float e, o;
                unpack2(accA[j], e, o);
                float dA = fmaf(-2.0f, e + o, z2A) + c2v;   // 2*cross exact (power of 2)
                if (dA < mvA) { mvA = dA; miA = k; }        // strict < => first index wins
                unpack2(accB[j], e, o);
                float dB = fmaf(-2.0f, e + o, z2B) + c2v;
                if (dB < mvB) { mvB = dB; miB = k; }
            }
        }
    }

    // Epilogue: gather z_q, write out, loss partials in double
    double lacc = 0.0;
    {
        const float4* qA = (const float4*)(cb + (size_t)miA * D);
        const float4* qB = (const float4*)(cb + (size_t)miB * D);
        float4* oA = (float4*)(out + rowA * D);
        float4* oB = (float4*)(out + rowB * D);
#pragma unroll
        for (int i = 0; i < D / 4; i++) {
            float4 a = qA[i];
            float x, y, u, w, d;
            unpack2(zpA[2 * i],     x, y);
            unpack2(zpA[2 * i + 1], u, w);
            d = a.x - x; lacc += (double)(d * d);
            d = a.y - y; lacc += (double)(d * d);
            d = a.z - u; lacc += (double)(d * d);
            d = a.w - w; lacc += (double)(d * d);
            oA[i] = a;
            float4 b = qB[i];
            unpack2(zpB[2 * i],     x, y);
            unpack2(zpB[2 * i + 1], u, w);
            d = b.x - x; lacc += (double)(d * d);
            d = b.y - y; lacc += (double)(d * d);
            d = b.z - u; lacc += (double)(d * d);
            d = b.w - w; lacc += (double)(d * d);
            oB[i] = b;
        }
    }

    if ((long)out_size >= (long)B * D + 1 + B) {
        const long iofs = (long)B * D + 1;
        out[iofs + rowA] = (float)miA;
        out[iofs + rowB] = (float)miB;
    }

    // block-reduce loss partials (reuse smem), one atomic per CTA
    __syncthreads();
    double* sd = (double*)sm;
    sd[t] = lacc;
    __syncthreads();
#pragma unroll
    for (int off = THREADS / 2; off >= 1; off >>= 1) {
        if (t < off) sd[t] += sd[t + off];
        __syncthreads();
    }
    if (t == 0) {
        atomicAdd(&g_loss, sd[0]);
        __threadfence();
        unsigned v = atomicAdd(&g_done, 1u);
        if (v == gridDim.x - 1) {       // last CTA finalizes loss
            g_done = 0u;
            if ((long)out_size >= (long)B * D + 1) {
                float m = (float)(g_loss / (double)((long)B * D));
                out[(size_t)B * D] = m + 0.25f * m;
            }
        }
    }
}

extern "C" void kernel_launch(void* const* d_in, const int* in_sizes, int n_in,
                              void* d_out, int out_size) {
    const float* z  = (const float*)d_in[0];
    const float* cb = (const float*)d_in[1];
    float* out = (float*)d_out;
    const int B = in_sizes[0] / D;

    const size_t smem = (size_t)CHUNK * D * sizeof(float) + K_CODES * sizeof(float);
    cudaFuncSetAttribute(vq_main, cudaFuncAttributeMaxDynamicSharedMemorySize, (int)smem);

    vq_prep<<<K_CODES, D>>>(cb);
    vq_main<<<B / ROWS_CTA, THREADS, smem>>>(z, cb, out, B, out_size);
}